// round 2
// baseline (speedup 1.0000x reference)
#include <cuda_runtime.h>
#include <stdint.h>

#define NN 100000
#define EE 1600000
#define HH 128
#define GG 512
#define CC 10
#define TOT (EE + NN)
#define BNEPS 1e-5f

// ---------------- scratch (static device globals; no allocation) ----------------
__device__ int   g_is64;
__device__ int   g_src32[EE];
__device__ int   g_dst32[EE];
__device__ int   g_batch32[NN];
__device__ int   g_deg[NN];
__device__ float g_dis[NN];
__device__ int   g_rowstart[NN + 1];
__device__ int   g_fill[NN];
__device__ int   g_blocksum[128];
__device__ int   g_blockoff[128];
__device__ int   g_csr_src[TOT];
__device__ float g_csr_norm[TOT];
__device__ float g_bufA[(size_t)NN * HH];   // GEMM output (h @ W)
__device__ float g_bufB[(size_t)NN * HH];   // aggregation output (pre-BN)
__device__ float g_psum[256 * HH];
__device__ float g_psq[256 * HH];
__device__ float g_scale[3][HH];
__device__ float g_shift[3][HH];
__device__ float g_pooled[GG * HH];
__device__ int   g_counts[GG];
__device__ float g_scaleP[HH];
__device__ float g_shiftP[HH];

// ---------------- prep kernels ----------------
__global__ void k_detect(const void* ei) {
    if (threadIdx.x == 0 && blockIdx.x == 0) {
        const long long* p = (const long long*)ei;
        int ok = 1;
        for (int i = 0; i < 256; i++) {
            long long v = p[i];
            if (v < 0 || v >= NN) { ok = 0; break; }
        }
        g_is64 = ok;
    }
}

__global__ void k_cvt_edges(const void* ei) {   // convert + degree count fused
    int e = blockIdx.x * blockDim.x + threadIdx.x;
    if (e >= EE) return;
    int s, d;
    if (g_is64) {
        const long long* p = (const long long*)ei;
        s = (int)p[e];
        d = (int)p[EE + e];
    } else {
        const int* p = (const int*)ei;
        s = p[e];
        d = p[EE + e];
    }
    g_src32[e] = s;
    g_dst32[e] = d;
    atomicAdd(&g_deg[d], 1);
}

__global__ void k_cvt_batch(const void* bt) {
    int i = blockIdx.x * blockDim.x + threadIdx.x;
    if (i >= NN) return;
    if (g_is64) g_batch32[i] = (int)((const long long*)bt)[i];
    else        g_batch32[i] = ((const int*)bt)[i];
}

__global__ void k_init_deg() {
    int i = blockIdx.x * blockDim.x + threadIdx.x;
    if (i < NN) g_deg[i] = 1;   // self-loop
}

__global__ void k_dis() {
    int i = blockIdx.x * blockDim.x + threadIdx.x;
    if (i < NN) g_dis[i] = rsqrtf((float)g_deg[i]);   // deg >= 1 always
}

__global__ void k_scan1() {
    __shared__ int s[1024];
    int i = blockIdx.x * 1024 + threadIdx.x;
    int v = (i < NN) ? g_deg[i] : 0;
    s[threadIdx.x] = v;
    __syncthreads();
    for (int off = 1; off < 1024; off <<= 1) {
        int t = (threadIdx.x >= off) ? s[threadIdx.x - off] : 0;
        __syncthreads();
        s[threadIdx.x] += t;
        __syncthreads();
    }
    if (i < NN) g_rowstart[i] = s[threadIdx.x];        // inclusive within chunk
    if (threadIdx.x == 1023) g_blocksum[blockIdx.x] = s[1023];
}

__global__ void k_scan2() {
    __shared__ int s[128];
    int t = threadIdx.x;
    int v = (t < 98) ? g_blocksum[t] : 0;
    s[t] = v;
    __syncthreads();
    for (int off = 1; off < 128; off <<= 1) {
        int tv = (t >= off) ? s[t - off] : 0;
        __syncthreads();
        s[t] += tv;
        __syncthreads();
    }
    g_blockoff[t] = s[t] - v;   // exclusive
}

__global__ void k_scan3() {
    int i = blockIdx.x * 1024 + threadIdx.x;
    if (i < NN) {
        g_rowstart[i] = g_rowstart[i] - g_deg[i] + g_blockoff[blockIdx.x]; // exclusive
        if (i == NN - 1) g_rowstart[NN] = TOT;
    }
}

__global__ void k_self() {
    int i = blockIdx.x * blockDim.x + threadIdx.x;
    if (i >= NN) return;
    int rs = g_rowstart[i];
    float d = g_dis[i];
    g_csr_src[rs] = i;
    g_csr_norm[rs] = d * d;
    g_fill[i] = 1;
}

__global__ void k_build() {
    int e = blockIdx.x * blockDim.x + threadIdx.x;
    if (e >= EE) return;
    int s = g_src32[e], d = g_dst32[e];
    int p = atomicAdd(&g_fill[d], 1);
    int idx = g_rowstart[d] + p;
    g_csr_src[idx] = s;
    g_csr_norm[idx] = g_dis[s] * g_dis[d];
}

// ---------------- tensor-core GEMM (split-TF32, near-fp32 accuracy) ----------------
__device__ __forceinline__ void split_tf32(float x, uint32_t& hi, uint32_t& lo) {
    asm("cvt.rna.tf32.f32 %0, %1;" : "=r"(hi) : "f"(x));
    float l = x - __uint_as_float(hi);
    asm("cvt.rna.tf32.f32 %0, %1;" : "=r"(lo) : "f"(l));
}

#define MMA_TF32(d, A0, A1, A2, A3, B0, B1)                              \
    asm volatile(                                                        \
        "mma.sync.aligned.m16n8k8.row.col.f32.tf32.tf32.f32 "            \
        "{%0,%1,%2,%3},{%4,%5,%6,%7},{%8,%9},{%0,%1,%2,%3};"             \
        : "+f"(d[0]), "+f"(d[1]), "+f"(d[2]), "+f"(d[3])                 \
        : "r"(A0), "r"(A1), "r"(A2), "r"(A3), "r"(B0), "r"(B1))

// C[N,128] = T(A)[N,128] @ W[128,128]; T = identity or fused BN(scale,shift)+ReLU.
template <bool TR>
__device__ __forceinline__ void gemm_tc(const float* __restrict__ A,
                                        const float* __restrict__ Wm,
                                        float* __restrict__ Cm,
                                        const float* __restrict__ scl,
                                        const float* __restrict__ shf) {
    // As4[r][kk*4+t] = (hi[k], lo[k], hi[k+4], lo[k+4]), k = kk*8 + t, stride 12 (pad)
    __shared__ float4 As4[128][12];
    __shared__ float4 Bs4[2][128][4];   // [kk][n][t]
    __shared__ float s_sc[128], s_sh[128];
    const int tid = threadIdx.x;
    const int lane = tid & 31, w = tid >> 5;
    const int l4 = lane >> 2, t = lane & 3;
    const int m0 = w * 16;
    const int row0 = blockIdx.x * 128;
    if (TR) {
        if (tid < 128) { s_sc[tid] = scl[tid]; s_sh[tid] = shf[tid]; }
        __syncthreads();
    }
    float acc[16][4];
#pragma unroll
    for (int i = 0; i < 16; i++)
#pragma unroll
        for (int j = 0; j < 4; j++) acc[i][j] = 0.f;

    for (int k0 = 0; k0 < 128; k0 += 16) {
        // stage A tile: 128 rows x 16 k
#pragma unroll
        for (int i = 0; i < 2; i++) {
            int idx = tid + i * 256;            // 0..511
            int r = idx >> 2, q = idx & 3;      // q-th float4 in row (k local q*4..q*4+3)
            float4 v = make_float4(0.f, 0.f, 0.f, 0.f);
            int gr = row0 + r;
            if (gr < NN) v = *(const float4*)(A + (size_t)gr * 128 + k0 + q * 4);
            if (TR) {
                int kk = k0 + q * 4;
                v.x = fmaxf(fmaf(v.x, s_sc[kk + 0], s_sh[kk + 0]), 0.f);
                v.y = fmaxf(fmaf(v.y, s_sc[kk + 1], s_sh[kk + 1]), 0.f);
                v.z = fmaxf(fmaf(v.z, s_sc[kk + 2], s_sh[kk + 2]), 0.f);
                v.w = fmaxf(fmaf(v.w, s_sc[kk + 3], s_sh[kk + 3]), 0.f);
            }
            float vv[4] = {v.x, v.y, v.z, v.w};
#pragma unroll
            for (int j = 0; j < 4; j++) {
                uint32_t hi, lo;
                split_tf32(vv[j], hi, lo);
                *(float2*)((char*)&As4[r][(q >> 1) * 4 + j] + (q & 1) * 8) =
                    make_float2(__uint_as_float(hi), __uint_as_float(lo));
            }
        }
        // stage B tile: 16 k x 128 n
#pragma unroll
        for (int i = 0; i < 2; i++) {
            int idx = tid + i * 256;
            int kr = idx >> 5, nq = idx & 31;
            float4 v = *(const float4*)(Wm + (size_t)(k0 + kr) * 128 + nq * 4);
            float vv[4] = {v.x, v.y, v.z, v.w};
            int kkI = kr >> 3, tt = kr & 3, half = (kr >> 2) & 1;
#pragma unroll
            for (int j = 0; j < 4; j++) {
                uint32_t hi, lo;
                split_tf32(vv[j], hi, lo);
                *(float2*)((char*)&Bs4[kkI][nq * 4 + j][tt] + half * 8) =
                    make_float2(__uint_as_float(hi), __uint_as_float(lo));
            }
        }
        __syncthreads();
#pragma unroll
        for (int kk = 0; kk < 2; kk++) {
            float4 a0 = As4[m0 + l4][kk * 4 + t];
            float4 a1 = As4[m0 + l4 + 8][kk * 4 + t];
            uint32_t ah0 = __float_as_uint(a0.x), ah1 = __float_as_uint(a1.x);
            uint32_t ah2 = __float_as_uint(a0.z), ah3 = __float_as_uint(a1.z);
            uint32_t al0 = __float_as_uint(a0.y), al1 = __float_as_uint(a1.y);
            uint32_t al2 = __float_as_uint(a0.w), al3 = __float_as_uint(a1.w);
#pragma unroll
            for (int nt = 0; nt < 16; nt++) {
                float4 b = Bs4[kk][nt * 8 + l4][t];
                uint32_t bh0 = __float_as_uint(b.x), bh1 = __float_as_uint(b.z);
                uint32_t bl0 = __float_as_uint(b.y), bl1 = __float_as_uint(b.w);
                MMA_TF32(acc[nt], ah0, ah1, ah2, ah3, bh0, bh1);
                MMA_TF32(acc[nt], ah0, ah1, ah2, ah3, bl0, bl1);
                MMA_TF32(acc[nt], al0, al1, al2, al3, bh0, bh1);
            }
        }
        __syncthreads();
    }
    // epilogue
    int r0 = row0 + m0 + l4;
    int r1 = r0 + 8;
#pragma unroll
    for (int nt = 0; nt < 16; nt++) {
        int c = nt * 8 + 2 * t;
        if (r0 < NN) *(float2*)(Cm + (size_t)r0 * 128 + c) = make_float2(acc[nt][0], acc[nt][1]);
        if (r1 < NN) *(float2*)(Cm + (size_t)r1 * 128 + c) = make_float2(acc[nt][2], acc[nt][3]);
    }
}

__global__ __launch_bounds__(256) void k_gemm_x(const float* __restrict__ A,
                                                const float* __restrict__ Wm) {
    gemm_tc<false>(A, Wm, g_bufA, nullptr, nullptr);
}

template <int L>
__global__ __launch_bounds__(256) void k_gemm_h(const float* __restrict__ Wm) {
    gemm_tc<true>(g_bufB, Wm, g_bufA, g_scale[L], g_shift[L]);
}

// ---------------- aggregation: bufB[dst] = sum_{e in CSR(dst)} norm_e * bufA[src_e] ----------------
__global__ __launch_bounds__(256) void k_agg() {
    int gt = blockIdx.x * blockDim.x + threadIdx.x;
    int w = gt >> 5, lane = gt & 31;
    if (w >= NN) return;
    int s0 = g_rowstart[w], s1 = g_rowstart[w + 1];
    int fo = lane * 4;
    float4 acc = make_float4(0.f, 0.f, 0.f, 0.f);
    for (int j = s0; j < s1; j++) {
        int src = g_csr_src[j];
        float nm = g_csr_norm[j];
        float4 v = *(const float4*)(g_bufA + (size_t)src * 128 + fo);
        acc.x = fmaf(nm, v.x, acc.x);
        acc.y = fmaf(nm, v.y, acc.y);
        acc.z = fmaf(nm, v.z, acc.z);
        acc.w = fmaf(nm, v.w, acc.w);
    }
    *(float4*)(g_bufB + (size_t)w * 128 + fo) = acc;
}

// ---------------- BatchNorm stats over bufB (per-feature, N rows) ----------------
__global__ void k_stats1() {
    int f = threadIdx.x;          // 128
    int b = blockIdx.x;           // 256
    float s = 0.f, q = 0.f;
    for (int r = b; r < NN; r += 256) {
        float v = g_bufB[(size_t)r * 128 + f];
        s += v;
        q = fmaf(v, v, q);
    }
    g_psum[b * 128 + f] = s;
    g_psq[b * 128 + f] = q;
}

__global__ void k_stats2(const float* __restrict__ gamma,
                         const float* __restrict__ beta, int L) {
    int f = threadIdx.x;
    float s = 0.f, q = 0.f;
    for (int b = 0; b < 256; b++) { s += g_psum[b * 128 + f]; q += g_psq[b * 128 + f]; }
    float m = s / (float)NN;
    float var = fmaxf(q / (float)NN - m * m, 0.f);
    float sc = gamma[f] * rsqrtf(var + BNEPS);
    g_scale[L][f] = sc;
    g_shift[L][f] = beta[f] - m * sc;   // GCN bias cancels inside BN
}

// ---------------- pooling ----------------
__global__ void k_zero_pool() {
    int i = blockIdx.x * blockDim.x + threadIdx.x;
    if (i < GG * HH) g_pooled[i] = 0.f;
    if (i < GG) g_counts[i] = 0;
}

__global__ __launch_bounds__(256) void k_pool() {
    int gt = blockIdx.x * blockDim.x + threadIdx.x;
    int w = gt >> 5, lane = gt & 31;
    if (w >= NN) return;
    int g = g_batch32[w];
    int fo = lane * 4;
    float4 v = *(const float4*)(g_bufB + (size_t)w * 128 + fo);
    float4 sc = *(const float4*)&g_scale[2][fo];
    float4 sh = *(const float4*)&g_shift[2][fo];
    v.x = fmaxf(fmaf(v.x, sc.x, sh.x), 0.f);
    v.y = fmaxf(fmaf(v.y, sc.y, sh.y), 0.f);
    v.z = fmaxf(fmaf(v.z, sc.z, sh.z), 0.f);
    v.w = fmaxf(fmaf(v.w, sc.w, sh.w), 0.f);
    float* base = g_pooled + (size_t)g * 128 + fo;
    atomicAdd(base + 0, v.x);
    atomicAdd(base + 1, v.y);
    atomicAdd(base + 2, v.z);
    atomicAdd(base + 3, v.w);
    if (lane == 0) atomicAdd(&g_counts[g], 1);
}

__global__ void k_pool_fin() {
    int i = blockIdx.x * blockDim.x + threadIdx.x;
    if (i >= GG * HH) return;
    int g = i >> 7;
    int c = g_counts[g];
    g_pooled[i] *= 1.f / (float)(c > 0 ? c : 1);
}

// ---------------- head ----------------
__global__ void k_headstats(const float* __restrict__ gp,
                            const float* __restrict__ bep) {
    int f = threadIdx.x;
    float s = 0.f, q = 0.f;
    for (int r = 0; r < GG; r++) {
        float v = g_pooled[(size_t)r * 128 + f];
        s += v;
        q = fmaf(v, v, q);
    }
    float m = s / (float)GG;
    float var = fmaxf(q / (float)GG - m * m, 0.f);
    float sc = gp[f] * rsqrtf(var + BNEPS);
    g_scaleP[f] = sc;
    g_shiftP[f] = bep[f] - m * sc;
}

__global__ void k_head(const float* __restrict__ lw1, const float* __restrict__ lb1,
                       const float* __restrict__ lw2, const float* __restrict__ lb2,
                       float* __restrict__ out) {
    __shared__ float zn[128], y1[128], lg[CC], lse;
    int r = blockIdx.x, t = threadIdx.x;
    zn[t] = fmaf(g_pooled[(size_t)r * 128 + t], g_scaleP[t], g_shiftP[t]);
    __syncthreads();
    float a = lb1[t];
#pragma unroll 16
    for (int k = 0; k < 128; k++) a = fmaf(zn[k], lw1[(size_t)k * 128 + t], a);
    y1[t] = fmaxf(a, 0.f);
    __syncthreads();
    if (t < CC) {
        float a2 = lb2[t];
#pragma unroll 16
        for (int k = 0; k < 128; k++) a2 = fmaf(y1[k], lw2[(size_t)k * CC + t], a2);
        lg[t] = a2;
    }
    __syncthreads();
    if (t == 0) {
        float m = lg[0];
        for (int i = 1; i < CC; i++) m = fmaxf(m, lg[i]);
        float s = 0.f;
        for (int i = 0; i < CC; i++) s += expf(lg[i] - m);
        lse = m + logf(s);
    }
    __syncthreads();
    if (t < CC) out[(size_t)r * CC + t] = lg[t] - lse;
}

// ---------------- launch ----------------
extern "C" void kernel_launch(void* const* d_in, const int* in_sizes, int n_in,
                              void* d_out, int out_size) {
    const float* x   = (const float*)d_in[0];
    const void*  ei  = d_in[1];
    const void*  bt  = d_in[2];
    const float* W1  = (const float*)d_in[3];
    const float* g1  = (const float*)d_in[5];
    const float* be1 = (const float*)d_in[6];
    const float* W2  = (const float*)d_in[7];
    const float* g2  = (const float*)d_in[9];
    const float* be2 = (const float*)d_in[10];
    const float* W3  = (const float*)d_in[11];
    const float* g3  = (const float*)d_in[13];
    const float* be3 = (const float*)d_in[14];
    const float* gp  = (const float*)d_in[15];
    const float* bep = (const float*)d_in[16];
    const float* lw1 = (const float*)d_in[17];
    const float* lb1 = (const float*)d_in[18];
    const float* lw2 = (const float*)d_in[19];
    const float* lb2 = (const float*)d_in[20];
    float* out = (float*)d_out;

    const int NB  = (NN + 255) / 256;      // 391
    const int EB  = (EE + 255) / 256;      // 6250
    const int WB  = (NN * 32 + 255) / 256; // 12500
    const int GMB = (NN + 127) / 128;      // 782

    // graph prep (runs every replay)
    k_detect<<<1, 32>>>(ei);
    k_init_deg<<<NB, 256>>>();
    k_cvt_edges<<<EB, 256>>>(ei);          // convert + degree count
    k_cvt_batch<<<NB, 256>>>(bt);
    k_dis<<<NB, 256>>>();
    k_scan1<<<98, 1024>>>();
    k_scan2<<<1, 128>>>();
    k_scan3<<<98, 1024>>>();
    k_self<<<NB, 256>>>();
    k_build<<<EB, 256>>>();

    // layer 1
    k_gemm_x<<<GMB, 256>>>(x, W1);
    k_agg<<<WB, 256>>>();
    k_stats1<<<256, 128>>>();
    k_stats2<<<1, 128>>>(g1, be1, 0);
    // layer 2 (BN+ReLU of layer 1 fused into A load)
    k_gemm_h<0><<<GMB, 256>>>(W2);
    k_agg<<<WB, 256>>>();
    k_stats1<<<256, 128>>>();
    k_stats2<<<1, 128>>>(g2, be2, 1);
    // layer 3
    k_gemm_h<1><<<GMB, 256>>>(W3);
    k_agg<<<WB, 256>>>();
    k_stats1<<<256, 128>>>();
    k_stats2<<<1, 128>>>(g3, be3, 2);

    // pool (BN+ReLU of layer 3 fused into pooling loads)
    k_zero_pool<<<256, 256>>>();
    k_pool<<<WB, 256>>>();
    k_pool_fin<<<256, 256>>>();

    // head
    k_headstats<<<1, 128>>>(gp, bep);
    k_head<<<GG, 128>>>(lw1, lb1, lw2, lb2, out);
}

// round 4
// speedup vs baseline: 1.5232x; 1.5232x over previous
#include <cuda_runtime.h>
#include <cuda_bf16.h>
#include <stdint.h>

#define NN 100000
#define EE 1600000
#define HH 128
#define GG 512
#define CC 10
#define TOT (EE + NN)
#define BNEPS 1e-5f

// W^T padded bf16x2 layout: u32[n][68] (64 k-pairs + 4 pad)
#define WSTRIDE 68
#define WELEMS (128 * WSTRIDE)   // 8704 u32

// ---------------- scratch (static device globals; no allocation) ----------------
__device__ int   g_is64;
__device__ int   g_src32[EE];
__device__ int   g_dst32[EE];
__device__ int   g_batch32[NN];
__device__ int   g_deg[NN];
__device__ float g_dis[NN];
__device__ int   g_rowstart[NN + 1];
__device__ int   g_fill[NN];
__device__ int   g_blocksum[128];
__device__ int   g_blockoff[128];
__device__ int   g_csr_src[TOT];
__device__ float g_csr_norm[TOT];
__device__ float g_bufA[(size_t)NN * HH];   // GEMM output (h @ W)
__device__ float g_bufB[(size_t)NN * HH];   // aggregation output (pre-BN)
__device__ float g_psum[256 * HH];
__device__ float g_psq[256 * HH];
__device__ float g_scale[3][HH];
__device__ float g_shift[3][HH];
__device__ float g_pooled[GG * HH];
__device__ int   g_counts[GG];
__device__ float g_scaleP[HH];
__device__ float g_shiftP[HH];
__device__ __align__(16) uint32_t g_Whi32[WELEMS];
__device__ __align__(16) uint32_t g_Wlo32[WELEMS];

// ---------------- prep kernels ----------------
__global__ void k_detect(const void* ei) {
    if (threadIdx.x == 0 && blockIdx.x == 0) {
        const long long* p = (const long long*)ei;
        int ok = 1;
        for (int i = 0; i < 256; i++) {
            long long v = p[i];
            if (v < 0 || v >= NN) { ok = 0; break; }
        }
        g_is64 = ok;
    }
}

__global__ void k_cvt_edges(const void* ei) {   // convert + degree count fused
    int e = blockIdx.x * blockDim.x + threadIdx.x;
    if (e >= EE) return;
    int s, d;
    if (g_is64) {
        const long long* p = (const long long*)ei;
        s = (int)p[e];
        d = (int)p[EE + e];
    } else {
        const int* p = (const int*)ei;
        s = p[e];
        d = p[EE + e];
    }
    g_src32[e] = s;
    g_dst32[e] = d;
    atomicAdd(&g_deg[d], 1);
}

__global__ void k_cvt_batch(const void* bt) {
    int i = blockIdx.x * blockDim.x + threadIdx.x;
    if (i >= NN) return;
    if (g_is64) g_batch32[i] = (int)((const long long*)bt)[i];
    else        g_batch32[i] = ((const int*)bt)[i];
}

__global__ void k_init_deg() {
    int i = blockIdx.x * blockDim.x + threadIdx.x;
    if (i < NN) g_deg[i] = 1;   // self-loop
}

__global__ void k_dis() {
    int i = blockIdx.x * blockDim.x + threadIdx.x;
    if (i < NN) g_dis[i] = rsqrtf((float)g_deg[i]);
}

__global__ void k_scan1() {
    __shared__ int s[1024];
    int i = blockIdx.x * 1024 + threadIdx.x;
    int v = (i < NN) ? g_deg[i] : 0;
    s[threadIdx.x] = v;
    __syncthreads();
    for (int off = 1; off < 1024; off <<= 1) {
        int t = (threadIdx.x >= off) ? s[threadIdx.x - off] : 0;
        __syncthreads();
        s[threadIdx.x] += t;
        __syncthreads();
    }
    if (i < NN) g_rowstart[i] = s[threadIdx.x];
    if (threadIdx.x == 1023) g_blocksum[blockIdx.x] = s[1023];
}

__global__ void k_scan2() {
    __shared__ int s[128];
    int t = threadIdx.x;
    int v = (t < 98) ? g_blocksum[t] : 0;
    s[t] = v;
    __syncthreads();
    for (int off = 1; off < 128; off <<= 1) {
        int tv = (t >= off) ? s[t - off] : 0;
        __syncthreads();
        s[t] += tv;
        __syncthreads();
    }
    g_blockoff[t] = s[t] - v;
}

__global__ void k_scan3() {
    int i = blockIdx.x * 1024 + threadIdx.x;
    if (i < NN) {
        g_rowstart[i] = g_rowstart[i] - g_deg[i] + g_blockoff[blockIdx.x];
        if (i == NN - 1) g_rowstart[NN] = TOT;
    }
}

__global__ void k_self() {
    int i = blockIdx.x * blockDim.x + threadIdx.x;
    if (i >= NN) return;
    int rs = g_rowstart[i];
    float d = g_dis[i];
    g_csr_src[rs] = i;
    g_csr_norm[rs] = d * d;
    g_fill[i] = 1;
}

__global__ void k_build() {
    int e = blockIdx.x * blockDim.x + threadIdx.x;
    if (e >= EE) return;
    int s = g_src32[e], d = g_dst32[e];
    int p = atomicAdd(&g_fill[d], 1);
    int idx = g_rowstart[d] + p;
    g_csr_src[idx] = s;
    g_csr_norm[idx] = g_dis[s] * g_dis[d];
}

// ---------------- split-bf16 helpers ----------------
__device__ __forceinline__ uint32_t pack2(float a, float b, uint32_t& lo) {
    __nv_bfloat16 ha = __float2bfloat16(a), hb = __float2bfloat16(b);
    __nv_bfloat16 la = __float2bfloat16(a - __bfloat162float(ha));
    __nv_bfloat16 lb = __float2bfloat16(b - __bfloat162float(hb));
    lo = (uint32_t)__bfloat16_as_ushort(la) | ((uint32_t)__bfloat16_as_ushort(lb) << 16);
    return (uint32_t)__bfloat16_as_ushort(ha) | ((uint32_t)__bfloat16_as_ushort(hb) << 16);
}

// split W^T into padded bf16x2 hi/lo:  g_W*32[n*68 + kp] packs W[2kp][n], W[2kp+1][n]
__global__ void k_prepW(const float* __restrict__ W) {
    int idx = blockIdx.x * blockDim.x + threadIdx.x;   // 8192
    if (idx >= 128 * 64) return;
    int n = idx >> 6, kp = idx & 63;
    float v0 = W[(size_t)(kp * 2) * 128 + n];
    float v1 = W[(size_t)(kp * 2 + 1) * 128 + n];
    uint32_t lo, hi = pack2(v0, v1, lo);
    g_Whi32[n * WSTRIDE + kp] = hi;
    g_Wlo32[n * WSTRIDE + kp] = lo;
}

#define MMA_BF16(d, a0, a1, a2, a3, b0, b1)                              \
    asm volatile(                                                        \
        "mma.sync.aligned.m16n8k16.row.col.f32.bf16.bf16.f32 "           \
        "{%0,%1,%2,%3},{%4,%5,%6,%7},{%8,%9},{%0,%1,%2,%3};"             \
        : "+f"(d[0]), "+f"(d[1]), "+f"(d[2]), "+f"(d[3])                 \
        : "r"(a0), "r"(a1), "r"(a2), "r"(a3), "r"(b0), "r"(b1))

#define SMEM_DYN (4 * WELEMS * 4)   // Ahi, Alo, Bhi, Blo = 139264 B

// C[N,128] = T(A)[N,128] @ W[128,128]; T = identity or fused BN(scale,shift)+ReLU.
template <bool TR>
__device__ __forceinline__ void gemm_mma(const float* __restrict__ A,
                                         float* __restrict__ Cm,
                                         const float* __restrict__ scl,
                                         const float* __restrict__ shf) {
    extern __shared__ uint32_t sm[];
    uint32_t* Ahi = sm;
    uint32_t* Alo = sm + WELEMS;
    uint32_t* Bhi = sm + 2 * WELEMS;
    uint32_t* Blo = sm + 3 * WELEMS;
    __shared__ float s_sc[128], s_sh[128];

    const int tid = threadIdx.x;
    const int row0 = blockIdx.x * 128;

    if (TR && tid < 128) { s_sc[tid] = scl[tid]; s_sh[tid] = shf[tid]; }

    // copy pre-split W (uint4; 2176 uint4 per buffer)
    {
        const uint4* src_h = (const uint4*)g_Whi32;
        const uint4* src_l = (const uint4*)g_Wlo32;
        uint4* dst_h = (uint4*)Bhi;
        uint4* dst_l = (uint4*)Blo;
#pragma unroll
        for (int i = 0; i < 9; i++) {
            int q = tid + i * 256;
            if (q < WELEMS / 4) { dst_h[q] = src_h[q]; dst_l[q] = src_l[q]; }
        }
    }
    if (TR) __syncthreads();   // s_sc/s_sh visible for A staging

    // stage A: thread -> row r = tid/2, k-half kh (64 cols)
    {
        int r = tid >> 1;
        int kh = (tid & 1) << 6;
        int gr = row0 + r;
        const float* Arow = A + (size_t)gr * 128;
        uint32_t* ah = Ahi + r * WSTRIDE + (kh >> 1);
        uint32_t* al = Alo + r * WSTRIDE + (kh >> 1);
#pragma unroll
        for (int g = 0; g < 16; g++) {
            int k = kh + g * 4;
            float4 v = make_float4(0.f, 0.f, 0.f, 0.f);
            if (gr < NN) {
                v = *(const float4*)(Arow + k);
                if (TR) {
                    v.x = fmaxf(fmaf(v.x, s_sc[k + 0], s_sh[k + 0]), 0.f);
                    v.y = fmaxf(fmaf(v.y, s_sc[k + 1], s_sh[k + 1]), 0.f);
                    v.z = fmaxf(fmaf(v.z, s_sc[k + 2], s_sh[k + 2]), 0.f);
                    v.w = fmaxf(fmaf(v.w, s_sc[k + 3], s_sh[k + 3]), 0.f);
                }
            }
            uint32_t l0, l1;
            uint32_t h0 = pack2(v.x, v.y, l0);
            uint32_t h1 = pack2(v.z, v.w, l1);
            ah[g * 2] = h0; ah[g * 2 + 1] = h1;
            al[g * 2] = l0; al[g * 2 + 1] = l1;
        }
    }
    __syncthreads();

    // MMA: warp wid -> rows wid*16..+15; 16 n-tiles of 8; 8 k-chunks of 16
    const int wid = tid >> 5, lane = tid & 31;
    const int qr = lane >> 2, ql = lane & 3;
    const int mrow = wid * 16;
    float acc[16][4];
#pragma unroll
    for (int i = 0; i < 16; i++)
#pragma unroll
        for (int j = 0; j < 4; j++) acc[i][j] = 0.f;

    const uint32_t* Ah0 = Ahi + (mrow + qr) * WSTRIDE;
    const uint32_t* Ah1 = Ahi + (mrow + qr + 8) * WSTRIDE;
    const uint32_t* Al0 = Alo + (mrow + qr) * WSTRIDE;
    const uint32_t* Al1 = Alo + (mrow + qr + 8) * WSTRIDE;

#pragma unroll
    for (int kc = 0; kc < 8; kc++) {
        int kb = kc * 8;
        uint32_t ah0 = Ah0[kb + ql],     ah1 = Ah1[kb + ql];
        uint32_t ah2 = Ah0[kb + 4 + ql], ah3 = Ah1[kb + 4 + ql];
        uint32_t al0 = Al0[kb + ql],     al1 = Al1[kb + ql];
        uint32_t al2 = Al0[kb + 4 + ql], al3 = Al1[kb + 4 + ql];
#pragma unroll
        for (int nt = 0; nt < 16; nt++) {
            const uint32_t* Bh = Bhi + (nt * 8 + qr) * WSTRIDE;
            const uint32_t* Bl = Blo + (nt * 8 + qr) * WSTRIDE;
            uint32_t bh0 = Bh[kb + ql], bh1 = Bh[kb + 4 + ql];
            uint32_t bl0 = Bl[kb + ql], bl1 = Bl[kb + 4 + ql];
            MMA_BF16(acc[nt], ah0, ah1, ah2, ah3, bh0, bh1);
            MMA_BF16(acc[nt], ah0, ah1, ah2, ah3, bl0, bl1);
            MMA_BF16(acc[nt], al0, al1, al2, al3, bh0, bh1);
        }
    }

    // epilogue
    int r0 = row0 + mrow + qr;
    int r1 = r0 + 8;
#pragma unroll
    for (int nt = 0; nt < 16; nt++) {
        int c = nt * 8 + ql * 2;
        if (r0 < NN) *(float2*)(Cm + (size_t)r0 * 128 + c) = make_float2(acc[nt][0], acc[nt][1]);
        if (r1 < NN) *(float2*)(Cm + (size_t)r1 * 128 + c) = make_float2(acc[nt][2], acc[nt][3]);
    }
}

__global__ __launch_bounds__(256) void k_gemm_x(const float* __restrict__ A) {
    gemm_mma<false>(A, g_bufA, nullptr, nullptr);
}

template <int L>
__global__ __launch_bounds__(256) void k_gemm_h() {
    gemm_mma<true>(g_bufB, g_bufA, g_scale[L], g_shift[L]);
}

// ---------------- aggregation with fused BN partial stats ----------------
__global__ void k_zero_psum() {
    int i = blockIdx.x * blockDim.x + threadIdx.x;
    if (i < 256 * HH) { g_psum[i] = 0.f; g_psq[i] = 0.f; }
}

__global__ __launch_bounds__(256) void k_agg() {
    __shared__ float s_red[8][128];
    int gt = blockIdx.x * blockDim.x + threadIdx.x;
    int w = gt >> 5, lane = (threadIdx.x) & 31, wid = threadIdx.x >> 5;
    int s0 = g_rowstart[w], s1 = g_rowstart[w + 1];
    int fo = lane * 4;
    float4 acc = make_float4(0.f, 0.f, 0.f, 0.f);
    for (int j = s0; j < s1; j++) {
        int src = g_csr_src[j];
        float nm = g_csr_norm[j];
        float4 v = *(const float4*)(g_bufA + (size_t)src * 128 + fo);
        acc.x = fmaf(nm, v.x, acc.x);
        acc.y = fmaf(nm, v.y, acc.y);
        acc.z = fmaf(nm, v.z, acc.z);
        acc.w = fmaf(nm, v.w, acc.w);
    }
    *(float4*)(g_bufB + (size_t)w * 128 + fo) = acc;
    // block-level per-feature stats (NN = 12500 blocks * 8 rows exactly)
    *(float4*)&s_red[wid][fo] = acc;
    __syncthreads();
    int t = threadIdx.x;
    if (t < 128) {
        float s = 0.f, q = 0.f;
#pragma unroll
        for (int r = 0; r < 8; r++) {
            float v = s_red[r][t];
            s += v;
            q = fmaf(v, v, q);
        }
        int slot = (blockIdx.x & 255) * 128 + t;
        atomicAdd(&g_psum[slot], s);
        atomicAdd(&g_psq[slot], q);
    }
}

__global__ void k_stats2(const float* __restrict__ gamma,
                         const float* __restrict__ beta, int L) {
    int f = threadIdx.x;
    float s = 0.f, q = 0.f;
    for (int b = 0; b < 256; b++) { s += g_psum[b * 128 + f]; q += g_psq[b * 128 + f]; }
    float m = s / (float)NN;
    float var = fmaxf(q / (float)NN - m * m, 0.f);
    float sc = gamma[f] * rsqrtf(var + BNEPS);
    g_scale[L][f] = sc;
    g_shift[L][f] = beta[f] - m * sc;   // GCN bias cancels inside BN
}

// ---------------- pooling ----------------
__global__ void k_zero_pool() {
    int i = blockIdx.x * blockDim.x + threadIdx.x;
    if (i < GG * HH) g_pooled[i] = 0.f;
    if (i < GG) g_counts[i] = 0;
}

__global__ __launch_bounds__(256) void k_pool() {
    int gt = blockIdx.x * blockDim.x + threadIdx.x;
    int w = gt >> 5, lane = gt & 31;
    if (w >= NN) return;
    int g = g_batch32[w];
    int fo = lane * 4;
    float4 v = *(const float4*)(g_bufB + (size_t)w * 128 + fo);
    float4 sc = *(const float4*)&g_scale[2][fo];
    float4 sh = *(const float4*)&g_shift[2][fo];
    v.x = fmaxf(fmaf(v.x, sc.x, sh.x), 0.f);
    v.y = fmaxf(fmaf(v.y, sc.y, sh.y), 0.f);
    v.z = fmaxf(fmaf(v.z, sc.z, sh.z), 0.f);
    v.w = fmaxf(fmaf(v.w, sc.w, sh.w), 0.f);
    float* base = g_pooled + (size_t)g * 128 + fo;
    atomicAdd(base + 0, v.x);
    atomicAdd(base + 1, v.y);
    atomicAdd(base + 2, v.z);
    atomicAdd(base + 3, v.w);
    if (lane == 0) atomicAdd(&g_counts[g], 1);
}

__global__ void k_pool_fin() {
    int i = blockIdx.x * blockDim.x + threadIdx.x;
    if (i >= GG * HH) return;
    int g = i >> 7;
    int c = g_counts[g];
    g_pooled[i] *= 1.f / (float)(c > 0 ? c : 1);
}

// ---------------- head ----------------
__global__ void k_headstats(const float* __restrict__ gp,
                            const float* __restrict__ bep) {
    int f = threadIdx.x;
    float s = 0.f, q = 0.f;
    for (int r = 0; r < GG; r++) {
        float v = g_pooled[(size_t)r * 128 + f];
        s += v;
        q = fmaf(v, v, q);
    }
    float m = s / (float)GG;
    float var = fmaxf(q / (float)GG - m * m, 0.f);
    float sc = gp[f] * rsqrtf(var + BNEPS);
    g_scaleP[f] = sc;
    g_shiftP[f] = bep[f] - m * sc;
}

__global__ void k_head(const float* __restrict__ lw1, const float* __restrict__ lb1,
                       const float* __restrict__ lw2, const float* __restrict__ lb2,
                       float* __restrict__ out) {
    __shared__ float zn[128], y1[128], lg[CC], lse;
    int r = blockIdx.x, t = threadIdx.x;
    zn[t] = fmaf(g_pooled[(size_t)r * 128 + t], g_scaleP[t], g_shiftP[t]);
    __syncthreads();
    float a = lb1[t];
#pragma unroll 16
    for (int k = 0; k < 128; k++) a = fmaf(zn[k], lw1[(size_t)k * 128 + t], a);
    y1[t] = fmaxf(a, 0.f);
    __syncthreads();
    if (t < CC) {
        float a2 = lb2[t];
#pragma unroll 16
        for (int k = 0; k < 128; k++) a2 = fmaf(y1[k], lw2[(size_t)k * CC + t], a2);
        lg[t] = a2;
    }
    __syncthreads();
    if (t == 0) {
        float m = lg[0];
        for (int i = 1; i < CC; i++) m = fmaxf(m, lg[i]);
        float s = 0.f;
        for (int i = 0; i < CC; i++) s += expf(lg[i] - m);
        lse = m + logf(s);
    }
    __syncthreads();
    if (t < CC) out[(size_t)r * CC + t] = lg[t] - lse;
}

// ---------------- launch ----------------
extern "C" void kernel_launch(void* const* d_in, const int* in_sizes, int n_in,
                              void* d_out, int out_size) {
    const float* x   = (const float*)d_in[0];
    const void*  ei  = d_in[1];
    const void*  bt  = d_in[2];
    const float* W1  = (const float*)d_in[3];
    const float* g1  = (const float*)d_in[5];
    const float* be1 = (const float*)d_in[6];
    const float* W2  = (const float*)d_in[7];
    const float* g2  = (const float*)d_in[9];
    const float* be2 = (const float*)d_in[10];
    const float* W3  = (const float*)d_in[11];
    const float* g3  = (const float*)d_in[13];
    const float* be3 = (const float*)d_in[14];
    const float* gp  = (const float*)d_in[15];
    const float* bep = (const float*)d_in[16];
    const float* lw1 = (const float*)d_in[17];
    const float* lb1 = (const float*)d_in[18];
    const float* lw2 = (const float*)d_in[19];
    const float* lb2 = (const float*)d_in[20];
    float* out = (float*)d_out;

    static int attr_done = 0;
    if (!attr_done) {
        cudaFuncSetAttribute((const void*)k_gemm_x,
                             cudaFuncAttributeMaxDynamicSharedMemorySize, SMEM_DYN);
        cudaFuncSetAttribute((const void*)k_gemm_h<0>,
                             cudaFuncAttributeMaxDynamicSharedMemorySize, SMEM_DYN);
        cudaFuncSetAttribute((const void*)k_gemm_h<1>,
                             cudaFuncAttributeMaxDynamicSharedMemorySize, SMEM_DYN);
        attr_done = 1;
    }

    const int NB  = (NN + 255) / 256;      // 391
    const int EB  = (EE + 255) / 256;      // 6250
    const int WB  = (NN * 32 + 255) / 256; // 12500
    const int GMB = (NN + 127) / 128;      // 782

    // graph prep
    k_detect<<<1, 32>>>(ei);
    k_init_deg<<<NB, 256>>>();
    k_cvt_edges<<<EB, 256>>>(ei);
    k_cvt_batch<<<NB, 256>>>(bt);
    k_dis<<<NB, 256>>>();
    k_scan1<<<98, 1024>>>();
    k_scan2<<<1, 128>>>();
    k_scan3<<<98, 1024>>>();
    k_self<<<NB, 256>>>();
    k_build<<<EB, 256>>>();

    // layer 1
    k_prepW<<<32, 256>>>(W1);
    k_zero_psum<<<128, 256>>>();
    k_gemm_x<<<GMB, 256, SMEM_DYN>>>(x);
    k_agg<<<WB, 256>>>();
    k_stats2<<<1, 128>>>(g1, be1, 0);
    // layer 2 (BN+ReLU of layer 1 fused into A staging)
    k_prepW<<<32, 256>>>(W2);
    k_zero_psum<<<128, 256>>>();
    k_gemm_h<0><<<GMB, 256, SMEM_DYN>>>();
    k_agg<<<WB, 256>>>();
    k_stats2<<<1, 128>>>(g2, be2, 1);
    // layer 3
    k_prepW<<<32, 256>>>(W3);
    k_zero_psum<<<128, 256>>>();
    k_gemm_h<1><<<GMB, 256, SMEM_DYN>>>();
    k_agg<<<WB, 256>>>();
    k_stats2<<<1, 128>>>(g3, be3, 2);

    // pool (BN+ReLU of layer 3 fused into pooling loads)
    k_zero_pool<<<256, 256>>>();
    k_pool<<<WB, 256>>>();
    k_pool_fin<<<256, 256>>>();

    // head
    k_headstats<<<1, 128>>>(gp, bep);
    k_head<<<GG, 128>>>(lw1, lb1, lw2, lb2, out);
}